// round 3
// baseline (speedup 1.0000x reference)
#include <cuda_runtime.h>
#include <math.h>

#define BATCH 1024
#define ED 128
#define MAXN 200
#define PAD_IDX 100000
#define LN_EPS 1e-5f

__global__ __launch_bounds__(256, 6) void entity_encoder_kernel(
    const int*   __restrict__ entity,      // [BATCH, 2]
    const int*   __restrict__ conn_left,   // [BATCH, MAXN, 2]
    const int*   __restrict__ conn_right,  // [BATCH, MAXN, 2]
    const float* __restrict__ emb,         // [100001, ED]
    const float* __restrict__ W_bil,       // [ED, ED]
    const float* __restrict__ W_tail,      // [ED, ED]
    const float* __restrict__ W_head,      // [ED, ED]
    const float* __restrict__ gamma,       // [ED]
    const float* __restrict__ beta,        // [ED]
    float*       __restrict__ out)         // [2, BATCH, ED]
{
    const int b    = blockIdx.x;
    const int side = blockIdx.y;
    const int tid  = threadIdx.x;
    const int wid  = tid >> 5;
    const int lane = tid & 31;

    __shared__ float s_wr[ED];        // weak_rel
    __shared__ float s_head[ED];      // head embedding for this side
    __shared__ float s_qp[2 * ED];    // partial q (two 64-d halves)
    __shared__ float s_q[ED];         // q = wr @ W_bil
    __shared__ float s_sc[MAXN];      // scores -> att
    __shared__ float s_part[8 * ED];  // per-warp agg partials
    __shared__ float s_agg[ED];
    __shared__ float s_x[ED];
    __shared__ float s_redA[8];
    __shared__ float s_redB[8];
    __shared__ float s_stat[2];

    // ---- head / weak_rel ----
    const int e0 = entity[b * 2 + 0];
    const int e1 = entity[b * 2 + 1];
    if (tid < ED) {
        float a = emb[(long)e0 * ED + tid];
        float c = emb[(long)e1 * ED + tid];
        s_wr[tid]   = c - a;                    // head_right - head_left
        s_head[tid] = (side == 0) ? a : c;
    }
    __syncthreads();

    // ---- q[e] = sum_d wr[d] * W_bil[d, e]  (coalesced over e each iter) ----
    {
        const int e    = tid & (ED - 1);
        const int half = tid >> 7;          // 0 or 1
        const int d0   = half * 64;
        float acc = 0.f;
        #pragma unroll 8
        for (int d = 0; d < 64; ++d)
            acc = fmaf(s_wr[d0 + d], W_bil[(d0 + d) * ED + e], acc);
        s_qp[tid] = acc;
    }
    __syncthreads();
    if (tid < ED) s_q[tid] = s_qp[tid] + s_qp[ED + tid];
    __syncthreads();

    const int* conn = ((side == 0) ? conn_left : conn_right) + (long)b * MAXN * 2;

    // ---- scores: warp per neighbor, float4 gather + shuffle reduce ----
    {
        float4 q4 = ((const float4*)s_q)[lane];
        for (int m = wid; m < MAXN; m += 8) {
            int rid = conn[m * 2 + 0];
            float v;
            if (rid == PAD_IDX) {
                v = -INFINITY;
            } else {
                float4 r = ((const float4*)(emb + (long)rid * ED))[lane];
                v = q4.x * r.x + q4.y * r.y + q4.z * r.z + q4.w * r.w;
                v += __shfl_xor_sync(0xffffffffu, v, 16);
                v += __shfl_xor_sync(0xffffffffu, v, 8);
                v += __shfl_xor_sync(0xffffffffu, v, 4);
                v += __shfl_xor_sync(0xffffffffu, v, 2);
                v += __shfl_xor_sync(0xffffffffu, v, 1);
            }
            if (lane == 0) s_sc[m] = v;
        }
    }
    __syncthreads();

    // ---- softmax over 200 scores (block reduce) ----
    {
        float v = (tid < MAXN) ? s_sc[tid] : -INFINITY;
        float mx = v;
        mx = fmaxf(mx, __shfl_xor_sync(0xffffffffu, mx, 16));
        mx = fmaxf(mx, __shfl_xor_sync(0xffffffffu, mx, 8));
        mx = fmaxf(mx, __shfl_xor_sync(0xffffffffu, mx, 4));
        mx = fmaxf(mx, __shfl_xor_sync(0xffffffffu, mx, 2));
        mx = fmaxf(mx, __shfl_xor_sync(0xffffffffu, mx, 1));
        if (lane == 0) s_redA[wid] = mx;
        __syncthreads();
        if (tid == 0) {
            float m2 = -INFINITY;
            #pragma unroll
            for (int w = 0; w < 8; ++w) m2 = fmaxf(m2, s_redA[w]);
            s_stat[0] = m2;
        }
        __syncthreads();
        const float gmax = s_stat[0];
        float ev = (tid < MAXN) ? __expf(v - gmax) : 0.f;
        float sm = ev;
        sm += __shfl_xor_sync(0xffffffffu, sm, 16);
        sm += __shfl_xor_sync(0xffffffffu, sm, 8);
        sm += __shfl_xor_sync(0xffffffffu, sm, 4);
        sm += __shfl_xor_sync(0xffffffffu, sm, 2);
        sm += __shfl_xor_sync(0xffffffffu, sm, 1);
        if (lane == 0) s_redB[wid] = sm;
        __syncthreads();
        if (tid == 0) {
            float s = 0.f;
            #pragma unroll
            for (int w = 0; w < 8; ++w) s += s_redB[w];
            s_stat[1] = 1.f / s;
        }
        __syncthreads();
        if (tid < MAXN) s_sc[tid] = ev * s_stat[1];   // att
    }
    __syncthreads();

    // ---- agg = sum_m att[m] * emb[ent_id[m]] : warp per neighbor ----
    {
        float4 acc = make_float4(0.f, 0.f, 0.f, 0.f);
        for (int m = wid; m < MAXN; m += 8) {
            int   eid = conn[m * 2 + 1];
            float a   = s_sc[m];
            float4 t4 = ((const float4*)(emb + (long)eid * ED))[lane];
            acc.x = fmaf(a, t4.x, acc.x);
            acc.y = fmaf(a, t4.y, acc.y);
            acc.z = fmaf(a, t4.z, acc.z);
            acc.w = fmaf(a, t4.w, acc.w);
        }
        ((float4*)(s_part + wid * ED))[lane] = acc;
    }
    __syncthreads();
    if (tid < ED) {
        float s = 0.f;
        #pragma unroll
        for (int w = 0; w < 8; ++w) s += s_part[w * ED + tid];
        s_agg[tid] = s;
    }
    __syncthreads();

    // ---- h_i = relu(agg . W_tail[i,:] + head . W_head[i,:]); x = h + head ----
    {
        float4 a4 = ((const float4*)s_agg)[lane];
        float4 h4 = ((const float4*)s_head)[lane];
        for (int i = wid; i < ED; i += 8) {
            float4 wt = ((const float4*)(W_tail + i * ED))[lane];
            float4 wh = ((const float4*)(W_head + i * ED))[lane];
            float v = a4.x * wt.x + a4.y * wt.y + a4.z * wt.z + a4.w * wt.w
                    + h4.x * wh.x + h4.y * wh.y + h4.z * wh.z + h4.w * wh.w;
            v += __shfl_xor_sync(0xffffffffu, v, 16);
            v += __shfl_xor_sync(0xffffffffu, v, 8);
            v += __shfl_xor_sync(0xffffffffu, v, 4);
            v += __shfl_xor_sync(0xffffffffu, v, 2);
            v += __shfl_xor_sync(0xffffffffu, v, 1);
            if (lane == 0) s_x[i] = fmaxf(v, 0.f) + s_head[i];
        }
    }
    __syncthreads();

    // ---- LayerNorm over x[128] ----
    {
        float xv = (tid < ED) ? s_x[tid] : 0.f;
        float s1 = xv, s2 = xv * xv;
        s1 += __shfl_xor_sync(0xffffffffu, s1, 16);
        s2 += __shfl_xor_sync(0xffffffffu, s2, 16);
        s1 += __shfl_xor_sync(0xffffffffu, s1, 8);
        s2 += __shfl_xor_sync(0xffffffffu, s2, 8);
        s1 += __shfl_xor_sync(0xffffffffu, s1, 4);
        s2 += __shfl_xor_sync(0xffffffffu, s2, 4);
        s1 += __shfl_xor_sync(0xffffffffu, s1, 2);
        s2 += __shfl_xor_sync(0xffffffffu, s2, 2);
        s1 += __shfl_xor_sync(0xffffffffu, s1, 1);
        s2 += __shfl_xor_sync(0xffffffffu, s2, 1);
        if (lane == 0) { s_redA[wid] = s1; s_redB[wid] = s2; }
        __syncthreads();
        if (tid == 0) {
            float t1 = 0.f, t2 = 0.f;
            #pragma unroll
            for (int w = 0; w < 8; ++w) { t1 += s_redA[w]; t2 += s_redB[w]; }
            float mu  = t1 * (1.f / ED);
            float var = t2 * (1.f / ED) - mu * mu;
            s_stat[0] = mu;
            s_stat[1] = rsqrtf(var + LN_EPS);
        }
        __syncthreads();
        if (tid < ED) {
            float mu = s_stat[0], rstd = s_stat[1];
            float o = (s_x[tid] - mu) * rstd * gamma[tid] + beta[tid];
            out[((long)side * BATCH + b) * ED + tid] = o;
        }
    }
}

extern "C" void kernel_launch(void* const* d_in, const int* in_sizes, int n_in,
                              void* d_out, int out_size) {
    (void)in_sizes; (void)n_in; (void)out_size;
    const int*   entity     = (const int*)  d_in[0];
    const int*   conn_left  = (const int*)  d_in[1];
    const int*   conn_right = (const int*)  d_in[2];
    const float* emb        = (const float*)d_in[3];
    const float* W_bil      = (const float*)d_in[4];
    const float* W_tail     = (const float*)d_in[5];
    const float* W_head     = (const float*)d_in[6];
    const float* gamma      = (const float*)d_in[7];
    const float* beta       = (const float*)d_in[8];
    float* out = (float*)d_out;

    dim3 grid(BATCH, 2);
    entity_encoder_kernel<<<grid, 256>>>(entity, conn_left, conn_right, emb,
                                         W_bil, W_tail, W_head, gamma, beta, out);
}

// round 4
// speedup vs baseline: 1.3635x; 1.3635x over previous
#include <cuda_runtime.h>
#include <math.h>

#define BATCH 1024
#define ED 128
#define MAXN 200
#define PAD_IDX 100000
#define LN_EPS 1e-5f

__global__ __launch_bounds__(256, 5) void entity_encoder_kernel(
    const int*   __restrict__ entity,      // [BATCH, 2]
    const int*   __restrict__ conn_left,   // [BATCH, MAXN, 2]
    const int*   __restrict__ conn_right,  // [BATCH, MAXN, 2]
    const float* __restrict__ emb,         // [100001, ED]
    const float* __restrict__ W_bil,       // [ED, ED]
    const float* __restrict__ W_tail,      // [ED, ED]
    const float* __restrict__ W_head,      // [ED, ED]
    const float* __restrict__ gamma,       // [ED]
    const float* __restrict__ beta,        // [ED]
    float*       __restrict__ out)         // [2, BATCH, ED]
{
    const int b    = blockIdx.x;
    const int side = blockIdx.y;
    const int tid  = threadIdx.x;
    const int wid  = tid >> 5;
    const int lane = tid & 31;

    __shared__ float s_wr[ED];
    __shared__ float s_head[ED];
    __shared__ float s_qp[2 * ED];
    __shared__ float s_q[ED];
    __shared__ float s_sc[MAXN];
    __shared__ int   s_conn[2 * MAXN];    // interleaved (rel, ent)
    __shared__ float s_part[8 * ED];
    __shared__ float s_agg[ED];
    __shared__ float s_x[ED];
    __shared__ float s_redA[8];
    __shared__ float s_redB[8];
    __shared__ float s_stat[2];

    // ---- stage conn ids (coalesced) ----
    {
        const int* conn = ((side == 0) ? conn_left : conn_right) + (long)b * MAXN * 2;
        for (int i = tid; i < 2 * MAXN; i += 256) s_conn[i] = conn[i];
    }

    // ---- head / weak_rel ----
    const int e0 = entity[b * 2 + 0];
    const int e1 = entity[b * 2 + 1];
    if (tid < ED) {
        float a = emb[(long)e0 * ED + tid];
        float c = emb[(long)e1 * ED + tid];
        s_wr[tid]   = c - a;
        s_head[tid] = (side == 0) ? a : c;
    }
    __syncthreads();

    // ---- q[e] = sum_d wr[d] * W_bil[d, e] ----
    {
        const int e    = tid & (ED - 1);
        const int half = tid >> 7;
        const int d0   = half * 64;
        float acc = 0.f;
        #pragma unroll 8
        for (int d = 0; d < 64; ++d)
            acc = fmaf(s_wr[d0 + d], W_bil[(d0 + d) * ED + e], acc);
        s_qp[tid] = acc;
    }
    __syncthreads();
    if (tid < ED) s_q[tid] = s_qp[tid] + s_qp[ED + tid];
    __syncthreads();

    // ---- scores: warp per neighbor, 4 gathers in flight ----
    // warp handles m = wid + 8*j, j = 0..24  (24 = 6 groups of 4, +1 tail)
    {
        const float4 q4 = ((const float4*)s_q)[lane];
        #pragma unroll 1
        for (int g = 0; g < 6; ++g) {
            const int mb = wid + 32 * g;          // m = mb + 8*i
            int rid[4];
            #pragma unroll
            for (int i = 0; i < 4; ++i) rid[i] = s_conn[2 * (mb + 8 * i)];
            float4 r[4];
            #pragma unroll
            for (int i = 0; i < 4; ++i)
                r[i] = ((const float4*)(emb + (long)rid[i] * ED))[lane];
            #pragma unroll
            for (int i = 0; i < 4; ++i) {
                float v = q4.x * r[i].x + q4.y * r[i].y + q4.z * r[i].z + q4.w * r[i].w;
                v += __shfl_xor_sync(0xffffffffu, v, 16);
                v += __shfl_xor_sync(0xffffffffu, v, 8);
                v += __shfl_xor_sync(0xffffffffu, v, 4);
                v += __shfl_xor_sync(0xffffffffu, v, 2);
                v += __shfl_xor_sync(0xffffffffu, v, 1);
                if (lane == 0)
                    s_sc[mb + 8 * i] = (rid[i] == PAD_IDX) ? -INFINITY : v;
            }
        }
        // tail: j = 24
        {
            const int m   = wid + 192;
            const int rid = s_conn[2 * m];
            float4 r = ((const float4*)(emb + (long)rid * ED))[lane];
            float v = q4.x * r.x + q4.y * r.y + q4.z * r.z + q4.w * r.w;
            v += __shfl_xor_sync(0xffffffffu, v, 16);
            v += __shfl_xor_sync(0xffffffffu, v, 8);
            v += __shfl_xor_sync(0xffffffffu, v, 4);
            v += __shfl_xor_sync(0xffffffffu, v, 2);
            v += __shfl_xor_sync(0xffffffffu, v, 1);
            if (lane == 0)
                s_sc[m] = (rid == PAD_IDX) ? -INFINITY : v;
        }
    }
    __syncthreads();

    // ---- softmax over 200 scores ----
    {
        float v = (tid < MAXN) ? s_sc[tid] : -INFINITY;
        float mx = v;
        mx = fmaxf(mx, __shfl_xor_sync(0xffffffffu, mx, 16));
        mx = fmaxf(mx, __shfl_xor_sync(0xffffffffu, mx, 8));
        mx = fmaxf(mx, __shfl_xor_sync(0xffffffffu, mx, 4));
        mx = fmaxf(mx, __shfl_xor_sync(0xffffffffu, mx, 2));
        mx = fmaxf(mx, __shfl_xor_sync(0xffffffffu, mx, 1));
        if (lane == 0) s_redA[wid] = mx;
        __syncthreads();
        if (tid == 0) {
            float m2 = -INFINITY;
            #pragma unroll
            for (int w = 0; w < 8; ++w) m2 = fmaxf(m2, s_redA[w]);
            s_stat[0] = m2;
        }
        __syncthreads();
        const float gmax = s_stat[0];
        float ev = (tid < MAXN) ? __expf(v - gmax) : 0.f;
        float sm = ev;
        sm += __shfl_xor_sync(0xffffffffu, sm, 16);
        sm += __shfl_xor_sync(0xffffffffu, sm, 8);
        sm += __shfl_xor_sync(0xffffffffu, sm, 4);
        sm += __shfl_xor_sync(0xffffffffu, sm, 2);
        sm += __shfl_xor_sync(0xffffffffu, sm, 1);
        if (lane == 0) s_redB[wid] = sm;
        __syncthreads();
        if (tid == 0) {
            float s = 0.f;
            #pragma unroll
            for (int w = 0; w < 8; ++w) s += s_redB[w];
            s_stat[1] = 1.f / s;
        }
        __syncthreads();
        if (tid < MAXN) s_sc[tid] = ev * s_stat[1];
    }
    __syncthreads();

    // ---- agg = sum_m att[m] * emb[ent_id[m]] : 4 gathers in flight ----
    {
        float4 acc = make_float4(0.f, 0.f, 0.f, 0.f);
        #pragma unroll 1
        for (int g = 0; g < 6; ++g) {
            const int mb = wid + 32 * g;
            int eid[4];
            float a[4];
            #pragma unroll
            for (int i = 0; i < 4; ++i) {
                eid[i] = s_conn[2 * (mb + 8 * i) + 1];
                a[i]   = s_sc[mb + 8 * i];
            }
            float4 t[4];
            #pragma unroll
            for (int i = 0; i < 4; ++i)
                t[i] = ((const float4*)(emb + (long)eid[i] * ED))[lane];
            #pragma unroll
            for (int i = 0; i < 4; ++i) {
                acc.x = fmaf(a[i], t[i].x, acc.x);
                acc.y = fmaf(a[i], t[i].y, acc.y);
                acc.z = fmaf(a[i], t[i].z, acc.z);
                acc.w = fmaf(a[i], t[i].w, acc.w);
            }
        }
        {
            const int m   = wid + 192;
            const int eid = s_conn[2 * m + 1];
            const float a = s_sc[m];
            float4 t = ((const float4*)(emb + (long)eid * ED))[lane];
            acc.x = fmaf(a, t.x, acc.x);
            acc.y = fmaf(a, t.y, acc.y);
            acc.z = fmaf(a, t.z, acc.z);
            acc.w = fmaf(a, t.w, acc.w);
        }
        ((float4*)(s_part + wid * ED))[lane] = acc;
    }
    __syncthreads();
    if (tid < ED) {
        float s = 0.f;
        #pragma unroll
        for (int w = 0; w < 8; ++w) s += s_part[w * ED + tid];
        s_agg[tid] = s;
    }
    __syncthreads();

    // ---- h_i = relu(agg . W_tail[i,:] + head . W_head[i,:]); x = h + head ----
    {
        const float4 a4 = ((const float4*)s_agg)[lane];
        const float4 h4 = ((const float4*)s_head)[lane];
        #pragma unroll 1
        for (int i0 = wid; i0 < ED; i0 += 16) {
            const int i1 = i0 + 8;
            float4 wt0 = ((const float4*)(W_tail + i0 * ED))[lane];
            float4 wh0 = ((const float4*)(W_head + i0 * ED))[lane];
            float4 wt1 = ((const float4*)(W_tail + i1 * ED))[lane];
            float4 wh1 = ((const float4*)(W_head + i1 * ED))[lane];
            float v0 = a4.x * wt0.x + a4.y * wt0.y + a4.z * wt0.z + a4.w * wt0.w
                     + h4.x * wh0.x + h4.y * wh0.y + h4.z * wh0.z + h4.w * wh0.w;
            float v1 = a4.x * wt1.x + a4.y * wt1.y + a4.z * wt1.z + a4.w * wt1.w
                     + h4.x * wh1.x + h4.y * wh1.y + h4.z * wh1.z + h4.w * wh1.w;
            v0 += __shfl_xor_sync(0xffffffffu, v0, 16);
            v1 += __shfl_xor_sync(0xffffffffu, v1, 16);
            v0 += __shfl_xor_sync(0xffffffffu, v0, 8);
            v1 += __shfl_xor_sync(0xffffffffu, v1, 8);
            v0 += __shfl_xor_sync(0xffffffffu, v0, 4);
            v1 += __shfl_xor_sync(0xffffffffu, v1, 4);
            v0 += __shfl_xor_sync(0xffffffffu, v0, 2);
            v1 += __shfl_xor_sync(0xffffffffu, v1, 2);
            v0 += __shfl_xor_sync(0xffffffffu, v0, 1);
            v1 += __shfl_xor_sync(0xffffffffu, v1, 1);
            if (lane == 0) {
                s_x[i0] = fmaxf(v0, 0.f) + s_head[i0];
                s_x[i1] = fmaxf(v1, 0.f) + s_head[i1];
            }
        }
    }
    __syncthreads();

    // ---- LayerNorm over x[128] ----
    {
        float xv = (tid < ED) ? s_x[tid] : 0.f;
        float s1 = xv, s2 = xv * xv;
        s1 += __shfl_xor_sync(0xffffffffu, s1, 16);
        s2 += __shfl_xor_sync(0xffffffffu, s2, 16);
        s1 += __shfl_xor_sync(0xffffffffu, s1, 8);
        s2 += __shfl_xor_sync(0xffffffffu, s2, 8);
        s1 += __shfl_xor_sync(0xffffffffu, s1, 4);
        s2 += __shfl_xor_sync(0xffffffffu, s2, 4);
        s1 += __shfl_xor_sync(0xffffffffu, s1, 2);
        s2 += __shfl_xor_sync(0xffffffffu, s2, 2);
        s1 += __shfl_xor_sync(0xffffffffu, s1, 1);
        s2 += __shfl_xor_sync(0xffffffffu, s2, 1);
        if (lane == 0) { s_redA[wid] = s1; s_redB[wid] = s2; }
        __syncthreads();
        if (tid == 0) {
            float t1 = 0.f, t2 = 0.f;
            #pragma unroll
            for (int w = 0; w < 8; ++w) { t1 += s_redA[w]; t2 += s_redB[w]; }
            float mu  = t1 * (1.f / ED);
            float var = t2 * (1.f / ED) - mu * mu;
            s_stat[0] = mu;
            s_stat[1] = rsqrtf(var + LN_EPS);
        }
        __syncthreads();
        if (tid < ED) {
            float mu = s_stat[0], rstd = s_stat[1];
            float o = (s_x[tid] - mu) * rstd * gamma[tid] + beta[tid];
            out[((long)side * BATCH + b) * ED + tid] = o;
        }
    }
}

extern "C" void kernel_launch(void* const* d_in, const int* in_sizes, int n_in,
                              void* d_out, int out_size) {
    (void)in_sizes; (void)n_in; (void)out_size;
    const int*   entity     = (const int*)  d_in[0];
    const int*   conn_left  = (const int*)  d_in[1];
    const int*   conn_right = (const int*)  d_in[2];
    const float* emb        = (const float*)d_in[3];
    const float* W_bil      = (const float*)d_in[4];
    const float* W_tail     = (const float*)d_in[5];
    const float* W_head     = (const float*)d_in[6];
    const float* gamma      = (const float*)d_in[7];
    const float* beta       = (const float*)d_in[8];
    float* out = (float*)d_out;

    dim3 grid(BATCH, 2);
    entity_encoder_kernel<<<grid, 256>>>(entity, conn_left, conn_right, emb,
                                         W_bil, W_tail, W_head, gamma, beta, out);
}

// round 5
// speedup vs baseline: 1.4632x; 1.0731x over previous
#include <cuda_runtime.h>
#include <math.h>

#define BATCH 1024
#define ED 128
#define MAXN 200
#define PAD_IDX 100000
#define LN_EPS 1e-5f

__global__ __launch_bounds__(512, 2) void entity_encoder_kernel(
    const int*   __restrict__ entity,      // [BATCH, 2]
    const int*   __restrict__ conn_left,   // [BATCH, MAXN, 2]
    const int*   __restrict__ conn_right,  // [BATCH, MAXN, 2]
    const float* __restrict__ emb,         // [100001, ED]
    const float* __restrict__ W_bil,       // [ED, ED]
    const float* __restrict__ W_tail,      // [ED, ED]
    const float* __restrict__ W_head,      // [ED, ED]
    const float* __restrict__ gamma,       // [ED]
    const float* __restrict__ beta,        // [ED]
    float*       __restrict__ out)         // [2, BATCH, ED]
{
    const int b    = blockIdx.x;
    const int tid  = threadIdx.x;
    const int wid  = tid >> 5;
    const int lane = tid & 31;
    const int side = wid >> 3;      // 0 = left, 1 = right
    const int sw   = wid & 7;       // warp within side

    __shared__ float s_wr[ED];
    __shared__ float s_head[2][ED];
    __shared__ float s_qp[512];
    __shared__ float s_q[ED];
    __shared__ float s_sc[2][MAXN];
    __shared__ int   s_conn[2][2 * MAXN];
    __shared__ float s_part[16][ED];        // 8 KB
    __shared__ float s_agg[2][ED];
    __shared__ float s_x[2][ED];
    __shared__ float s_redA[2][8];
    __shared__ float s_redB[2][8];
    __shared__ float s_stat[2][2];

    // ---- stage conn ids (coalesced, both sides) ----
    {
        const long base = (long)b * MAXN * 2;
        for (int i = tid; i < 2 * MAXN; i += 512) {
            s_conn[0][i] = conn_left[base + i];
            s_conn[1][i] = conn_right[base + i];
        }
    }

    // ---- head / weak_rel ----
    const int e0 = entity[b * 2 + 0];
    const int e1 = entity[b * 2 + 1];
    if (tid < ED) {
        float a = emb[(long)e0 * ED + tid];
        float c = emb[(long)e1 * ED + tid];
        s_wr[tid]      = c - a;
        s_head[0][tid] = a;
        s_head[1][tid] = c;
    }
    __syncthreads();

    // ---- q[e] = sum_d wr[d] * W_bil[d, e]  (4-way d-split over 512 thr) ----
    {
        const int e  = tid & (ED - 1);
        const int qq = tid >> 7;            // 0..3
        const int d0 = qq * 32;
        float acc = 0.f;
        #pragma unroll 8
        for (int d = 0; d < 32; ++d)
            acc = fmaf(s_wr[d0 + d], W_bil[(d0 + d) * ED + e], acc);
        s_qp[tid] = acc;
    }
    __syncthreads();
    if (tid < ED)
        s_q[tid] = s_qp[tid] + s_qp[ED + tid] + s_qp[2 * ED + tid] + s_qp[3 * ED + tid];
    __syncthreads();

    // ---- scores: warp per neighbor (per side), 4 gathers in flight ----
    {
        const float4 q4 = ((const float4*)s_q)[lane];
        const int*   cn = s_conn[side];
        #pragma unroll 1
        for (int g = 0; g < 6; ++g) {
            const int mb = sw + 32 * g;
            int rid[4];
            #pragma unroll
            for (int i = 0; i < 4; ++i) rid[i] = cn[2 * (mb + 8 * i)];
            float4 r[4];
            #pragma unroll
            for (int i = 0; i < 4; ++i)
                r[i] = ((const float4*)(emb + (long)rid[i] * ED))[lane];
            #pragma unroll
            for (int i = 0; i < 4; ++i) {
                float v = q4.x * r[i].x + q4.y * r[i].y + q4.z * r[i].z + q4.w * r[i].w;
                v += __shfl_xor_sync(0xffffffffu, v, 16);
                v += __shfl_xor_sync(0xffffffffu, v, 8);
                v += __shfl_xor_sync(0xffffffffu, v, 4);
                v += __shfl_xor_sync(0xffffffffu, v, 2);
                v += __shfl_xor_sync(0xffffffffu, v, 1);
                if (lane == 0)
                    s_sc[side][mb + 8 * i] = (rid[i] == PAD_IDX) ? -INFINITY : v;
            }
        }
        {   // tail m = sw + 192
            const int m   = sw + 192;
            const int rid = cn[2 * m];
            float4 r = ((const float4*)(emb + (long)rid * ED))[lane];
            float v = q4.x * r.x + q4.y * r.y + q4.z * r.z + q4.w * r.w;
            v += __shfl_xor_sync(0xffffffffu, v, 16);
            v += __shfl_xor_sync(0xffffffffu, v, 8);
            v += __shfl_xor_sync(0xffffffffu, v, 4);
            v += __shfl_xor_sync(0xffffffffu, v, 2);
            v += __shfl_xor_sync(0xffffffffu, v, 1);
            if (lane == 0)
                s_sc[side][m] = (rid == PAD_IDX) ? -INFINITY : v;
        }
    }
    __syncthreads();

    // ---- two softmaxes in parallel (tid<256 -> side0, else side1) ----
    {
        const int sS = tid >> 8;            // 0 or 1
        const int t  = tid & 255;
        const int w8 = t >> 5;
        float v = (t < MAXN) ? s_sc[sS][t] : -INFINITY;
        float mx = v;
        mx = fmaxf(mx, __shfl_xor_sync(0xffffffffu, mx, 16));
        mx = fmaxf(mx, __shfl_xor_sync(0xffffffffu, mx, 8));
        mx = fmaxf(mx, __shfl_xor_sync(0xffffffffu, mx, 4));
        mx = fmaxf(mx, __shfl_xor_sync(0xffffffffu, mx, 2));
        mx = fmaxf(mx, __shfl_xor_sync(0xffffffffu, mx, 1));
        if (lane == 0) s_redA[sS][w8] = mx;
        __syncthreads();
        if (t == 0) {
            float m2 = -INFINITY;
            #pragma unroll
            for (int w = 0; w < 8; ++w) m2 = fmaxf(m2, s_redA[sS][w]);
            s_stat[sS][0] = m2;
        }
        __syncthreads();
        const float gmax = s_stat[sS][0];
        float ev = (t < MAXN) ? __expf(v - gmax) : 0.f;
        float sm = ev;
        sm += __shfl_xor_sync(0xffffffffu, sm, 16);
        sm += __shfl_xor_sync(0xffffffffu, sm, 8);
        sm += __shfl_xor_sync(0xffffffffu, sm, 4);
        sm += __shfl_xor_sync(0xffffffffu, sm, 2);
        sm += __shfl_xor_sync(0xffffffffu, sm, 1);
        if (lane == 0) s_redB[sS][w8] = sm;
        __syncthreads();
        if (t == 0) {
            float s = 0.f;
            #pragma unroll
            for (int w = 0; w < 8; ++w) s += s_redB[sS][w];
            s_stat[sS][1] = 1.f / s;
        }
        __syncthreads();
        if (t < MAXN) s_sc[sS][t] = ev * s_stat[sS][1];
    }
    __syncthreads();

    // ---- agg = sum_m att[m] * emb[ent_id[m]] : 4 gathers in flight ----
    {
        const int* cn = s_conn[side];
        float4 acc = make_float4(0.f, 0.f, 0.f, 0.f);
        #pragma unroll 1
        for (int g = 0; g < 6; ++g) {
            const int mb = sw + 32 * g;
            int eid[4];
            float a[4];
            #pragma unroll
            for (int i = 0; i < 4; ++i) {
                eid[i] = cn[2 * (mb + 8 * i) + 1];
                a[i]   = s_sc[side][mb + 8 * i];
            }
            float4 t[4];
            #pragma unroll
            for (int i = 0; i < 4; ++i)
                t[i] = ((const float4*)(emb + (long)eid[i] * ED))[lane];
            #pragma unroll
            for (int i = 0; i < 4; ++i) {
                acc.x = fmaf(a[i], t[i].x, acc.x);
                acc.y = fmaf(a[i], t[i].y, acc.y);
                acc.z = fmaf(a[i], t[i].z, acc.z);
                acc.w = fmaf(a[i], t[i].w, acc.w);
            }
        }
        {   // tail
            const int m   = sw + 192;
            const int eid = cn[2 * m + 1];
            const float a = s_sc[side][m];
            float4 t = ((const float4*)(emb + (long)eid * ED))[lane];
            acc.x = fmaf(a, t.x, acc.x);
            acc.y = fmaf(a, t.y, acc.y);
            acc.z = fmaf(a, t.z, acc.z);
            acc.w = fmaf(a, t.w, acc.w);
        }
        ((float4*)s_part[wid])[lane] = acc;
    }
    __syncthreads();
    if (tid < 256) {
        const int sR = tid >> 7;
        const int t  = tid & (ED - 1);
        float s = 0.f;
        #pragma unroll
        for (int w = 0; w < 8; ++w) s += s_part[sR * 8 + w][t];
        s_agg[sR][t] = s;
    }
    __syncthreads();

    // ---- h_i = relu(agg . W_tail[i,:] + head . W_head[i,:]) for BOTH sides
    //      (each W row loaded once, used twice) ----
    {
        const float4 aL = ((const float4*)s_agg[0])[lane];
        const float4 hL = ((const float4*)s_head[0])[lane];
        const float4 aR = ((const float4*)s_agg[1])[lane];
        const float4 hR = ((const float4*)s_head[1])[lane];
        #pragma unroll 1
        for (int i0 = wid; i0 < ED; i0 += 32) {
            const int i1 = i0 + 16;
            float4 wt0 = ((const float4*)(W_tail + i0 * ED))[lane];
            float4 wh0 = ((const float4*)(W_head + i0 * ED))[lane];
            float4 wt1 = ((const float4*)(W_tail + i1 * ED))[lane];
            float4 wh1 = ((const float4*)(W_head + i1 * ED))[lane];
            float vL0 = aL.x * wt0.x + aL.y * wt0.y + aL.z * wt0.z + aL.w * wt0.w
                      + hL.x * wh0.x + hL.y * wh0.y + hL.z * wh0.z + hL.w * wh0.w;
            float vR0 = aR.x * wt0.x + aR.y * wt0.y + aR.z * wt0.z + aR.w * wt0.w
                      + hR.x * wh0.x + hR.y * wh0.y + hR.z * wh0.z + hR.w * wh0.w;
            float vL1 = aL.x * wt1.x + aL.y * wt1.y + aL.z * wt1.z + aL.w * wt1.w
                      + hL.x * wh1.x + hL.y * wh1.y + hL.z * wh1.z + hL.w * wh1.w;
            float vR1 = aR.x * wt1.x + aR.y * wt1.y + aR.z * wt1.z + aR.w * wt1.w
                      + hR.x * wh1.x + hR.y * wh1.y + hR.z * wh1.z + hR.w * wh1.w;
            #pragma unroll
            for (int d = 16; d >= 1; d >>= 1) {
                vL0 += __shfl_xor_sync(0xffffffffu, vL0, d);
                vR0 += __shfl_xor_sync(0xffffffffu, vR0, d);
                vL1 += __shfl_xor_sync(0xffffffffu, vL1, d);
                vR1 += __shfl_xor_sync(0xffffffffu, vR1, d);
            }
            if (lane == 0) {
                s_x[0][i0] = fmaxf(vL0, 0.f) + s_head[0][i0];
                s_x[1][i0] = fmaxf(vR0, 0.f) + s_head[1][i0];
                s_x[0][i1] = fmaxf(vL1, 0.f) + s_head[0][i1];
                s_x[1][i1] = fmaxf(vR1, 0.f) + s_head[1][i1];
            }
        }
    }
    __syncthreads();

    // ---- two LayerNorms in parallel (tid<256: side = tid>>7) ----
    if (tid < 256) {
        const int sL = tid >> 7;
        const int t  = tid & (ED - 1);
        const int w4 = t >> 5;
        float xv = s_x[sL][t];
        float s1 = xv, s2 = xv * xv;
        #pragma unroll
        for (int d = 16; d >= 1; d >>= 1) {
            s1 += __shfl_xor_sync(0xffffffffu, s1, d);
            s2 += __shfl_xor_sync(0xffffffffu, s2, d);
        }
        if (lane == 0) { s_redA[sL][w4] = s1; s_redB[sL][w4] = s2; }
    }
    __syncthreads();
    if (tid < 256) {
        const int sL = tid >> 7;
        const int t  = tid & (ED - 1);
        if (t == 0) {
            float t1 = 0.f, t2 = 0.f;
            #pragma unroll
            for (int w = 0; w < 4; ++w) { t1 += s_redA[sL][w]; t2 += s_redB[sL][w]; }
            float mu  = t1 * (1.f / ED);
            float var = t2 * (1.f / ED) - mu * mu;
            s_stat[sL][0] = mu;
            s_stat[sL][1] = rsqrtf(var + LN_EPS);
        }
    }
    __syncthreads();
    if (tid < 256) {
        const int sL = tid >> 7;
        const int t  = tid & (ED - 1);
        float mu = s_stat[sL][0], rstd = s_stat[sL][1];
        float o = (s_x[sL][t] - mu) * rstd * gamma[t] + beta[t];
        out[((long)sL * BATCH + b) * ED + t] = o;
    }
}

extern "C" void kernel_launch(void* const* d_in, const int* in_sizes, int n_in,
                              void* d_out, int out_size) {
    (void)in_sizes; (void)n_in; (void)out_size;
    const int*   entity     = (const int*)  d_in[0];
    const int*   conn_left  = (const int*)  d_in[1];
    const int*   conn_right = (const int*)  d_in[2];
    const float* emb        = (const float*)d_in[3];
    const float* W_bil      = (const float*)d_in[4];
    const float* W_tail     = (const float*)d_in[5];
    const float* W_head     = (const float*)d_in[6];
    const float* gamma      = (const float*)d_in[7];
    const float* beta       = (const float*)d_in[8];
    float* out = (float*)d_out;

    entity_encoder_kernel<<<BATCH, 512>>>(entity, conn_left, conn_right, emb,
                                          W_bil, W_tail, W_head, gamma, beta, out);
}